// round 1
// baseline (speedup 1.0000x reference)
#include <cuda_runtime.h>
#include <math.h>

#define BATCH 2
#define SEQ 2048
#define DMODEL 1024
#define HEADS 16
#define DK 64

// Scratch: q,k,v,ctx in [B,S,D] layout (head h occupies columns h*64..h*64+63)
static __device__ float g_q[BATCH*SEQ*DMODEL];
static __device__ float g_k[BATCH*SEQ*DMODEL];
static __device__ float g_v[BATCH*SEQ*DMODEL];
static __device__ float g_ctx[BATCH*SEQ*DMODEL];

// Generic tiled fp32 GEMM, C = A @ op(B) * scale (+ bias), exact-tile dims.
// MODE 0: plain C[M,N] = A[M,K] @ B[N,K]^T + bias            (projections)
// MODE 1: per-(b,h) scores = q @ k^T * scale, C -> probs      (z = b*H+h)
// MODE 2: per-(b,h) ctx = probs @ v (B NOT transposed)        (z = b*H+h)
template<int M,int N,int K,int BM,int BN,int BK,int TM,int TN,int MODE>
__global__ void __launch_bounds__((BM/TM)*(BN/TN))
gemm_k(const float* __restrict__ A0, const float* __restrict__ B0,
       const float* __restrict__ bias, float* __restrict__ C0, float scale)
{
    constexpr int THREADS = (BM/TM)*(BN/TN);
    constexpr bool TRANSB = (MODE != 2);
    const int tid   = threadIdx.x;
    const int tileN = blockIdx.x * BN;
    const int tileM = blockIdx.y * BM;
    const int z     = blockIdx.z;

    const float* A  = A0;
    const float* Bp = B0;
    float*       C  = C0;
    int lda, ldb, ldc;
    if (MODE == 0) {
        lda = K; ldb = K; ldc = N;
    } else if (MODE == 1) {
        const int b = z / HEADS, h = z % HEADS;
        const size_t off = (size_t)b*SEQ*DMODEL + (size_t)h*DK;
        A = A0 + off; Bp = B0 + off;
        lda = DMODEL; ldb = DMODEL;
        C = C0 + (size_t)z*SEQ*SEQ; ldc = SEQ;
    } else {
        const int b = z / HEADS, h = z % HEADS;
        A = A0 + (size_t)z*SEQ*SEQ; lda = SEQ;
        Bp = B0 + (size_t)b*SEQ*DMODEL + (size_t)h*DK; ldb = DMODEL;
        C  = C0 + (size_t)b*SEQ*DMODEL + (size_t)h*DK; ldc = DMODEL;
    }

    __shared__ __align__(16) float As[BK][BM];
    __shared__ __align__(16) float Bs[BK][BN];

    const int tcol = tid % (BN/TN);
    const int trow = tid / (BN/TN);

    float acc[TM][TN];
    #pragma unroll
    for (int i = 0; i < TM; ++i)
        #pragma unroll
        for (int j = 0; j < TN; ++j)
            acc[i][j] = 0.f;

    for (int k0 = 0; k0 < K; k0 += BK) {
        // Load A tile (BM x BK), stored transposed As[k][m]
        #pragma unroll 2
        for (int i = tid; i < (BM*BK)/4; i += THREADS) {
            const int m  = i / (BK/4);
            const int k4 = (i % (BK/4)) * 4;
            float4 va = *(const float4*)(A + (size_t)(tileM+m)*lda + k0 + k4);
            As[k4+0][m] = va.x; As[k4+1][m] = va.y;
            As[k4+2][m] = va.z; As[k4+3][m] = va.w;
        }
        if (TRANSB) {
            // B is [N,K]: element (n,k) at Bp[n*ldb + k]
            #pragma unroll 2
            for (int i = tid; i < (BN*BK)/4; i += THREADS) {
                const int n  = i / (BK/4);
                const int k4 = (i % (BK/4)) * 4;
                float4 vb = *(const float4*)(Bp + (size_t)(tileN+n)*ldb + k0 + k4);
                Bs[k4+0][n] = vb.x; Bs[k4+1][n] = vb.y;
                Bs[k4+2][n] = vb.z; Bs[k4+3][n] = vb.w;
            }
        } else {
            // B is [K,N]: element (k,n) at Bp[k*ldb + n]
            #pragma unroll 2
            for (int i = tid; i < (BK*BN)/4; i += THREADS) {
                const int kk = i / (BN/4);
                const int n4 = (i % (BN/4)) * 4;
                float4 vb = *(const float4*)(Bp + (size_t)(k0+kk)*ldb + tileN + n4);
                *(float4*)&Bs[kk][n4] = vb;
            }
        }
        __syncthreads();

        #pragma unroll
        for (int kk = 0; kk < BK; ++kk) {
            float a[TM], b[TN];
            #pragma unroll
            for (int i = 0; i < TM; i += 4)
                *(float4*)&a[i] = *(const float4*)&As[kk][trow*TM + i];
            #pragma unroll
            for (int j = 0; j < TN; j += 4)
                *(float4*)&b[j] = *(const float4*)&Bs[kk][tcol*TN + j];
            #pragma unroll
            for (int i = 0; i < TM; ++i)
                #pragma unroll
                for (int j = 0; j < TN; ++j)
                    acc[i][j] = fmaf(a[i], b[j], acc[i][j]);
        }
        __syncthreads();
    }

    #pragma unroll
    for (int i = 0; i < TM; ++i) {
        const int row = tileM + trow*TM + i;
        #pragma unroll
        for (int j = 0; j < TN; ++j) {
            const int col = tileN + tcol*TN + j;
            float v = acc[i][j] * scale;
            if (MODE == 0) v += bias[col];
            C[(size_t)row*ldc + col] = v;
        }
    }
}

// In-place row softmax over rows of length SEQ=2048. One block (256 thr) per row.
__global__ void __launch_bounds__(256) softmax_k(float* __restrict__ p)
{
    const int row = blockIdx.x;
    float* r = p + (size_t)row * SEQ;
    const int tid = threadIdx.x;

    float x[8];
    float mx = -1e30f;
    #pragma unroll
    for (int i = 0; i < 8; ++i) {
        x[i] = r[tid + i*256];
        mx = fmaxf(mx, x[i]);
    }
    #pragma unroll
    for (int o = 16; o; o >>= 1) mx = fmaxf(mx, __shfl_xor_sync(0xffffffffu, mx, o));

    __shared__ float red[8];
    if ((tid & 31) == 0) red[tid >> 5] = mx;
    __syncthreads();
    float m = red[0];
    #pragma unroll
    for (int j = 1; j < 8; ++j) m = fmaxf(m, red[j]);
    __syncthreads();

    float s = 0.f;
    #pragma unroll
    for (int i = 0; i < 8; ++i) { x[i] = expf(x[i] - m); s += x[i]; }
    #pragma unroll
    for (int o = 16; o; o >>= 1) s += __shfl_xor_sync(0xffffffffu, s, o);
    if ((tid & 31) == 0) red[tid >> 5] = s;
    __syncthreads();
    float tot = 0.f;
    #pragma unroll
    for (int j = 0; j < 8; ++j) tot += red[j];
    const float inv = 1.0f / tot;

    #pragma unroll
    for (int i = 0; i < 8; ++i) r[tid + i*256] = x[i] * inv;
}

extern "C" void kernel_launch(void* const* d_in, const int* in_sizes, int n_in,
                              void* d_out, int out_size)
{
    const float* Q  = (const float*)d_in[0];
    const float* K_ = (const float*)d_in[1];
    const float* V  = (const float*)d_in[2];
    const float* Wq = (const float*)d_in[3];
    const float* bq = (const float*)d_in[4];
    const float* Wk = (const float*)d_in[5];
    const float* bk = (const float*)d_in[6];
    const float* Wv = (const float*)d_in[7];
    const float* bv = (const float*)d_in[8];
    const float* Wo = (const float*)d_in[9];
    const float* bo = (const float*)d_in[10];

    float* probs = (float*)d_out;                                  // [B,H,S,S]
    float* out   = probs + (size_t)BATCH*HEADS*SEQ*SEQ;            // [B,S,D]

    float *gq, *gk, *gv, *gctx;
    cudaGetSymbolAddress((void**)&gq,  g_q);
    cudaGetSymbolAddress((void**)&gk,  g_k);
    cudaGetSymbolAddress((void**)&gv,  g_v);
    cudaGetSymbolAddress((void**)&gctx, g_ctx);

    const dim3 t(256);

    // Projections: [4096,1024] @ W^T + b  -> scratch ([B,S,D] layout)
    gemm_k<4096,1024,1024,128,128,16,8,8,0><<<dim3(8,32,1), t>>>(Q,  Wq, bq, gq,  1.f);
    gemm_k<4096,1024,1024,128,128,16,8,8,0><<<dim3(8,32,1), t>>>(K_, Wk, bk, gk,  1.f);
    gemm_k<4096,1024,1024,128,128,16,8,8,0><<<dim3(8,32,1), t>>>(V,  Wv, bv, gv,  1.f);

    // Scores: per (b,h): q @ k^T * (1/8)  -> probs region (raw scores)
    gemm_k<2048,2048,64,128,128,16,8,8,1><<<dim3(16,16,32), t>>>(gq, gk, nullptr, probs, 0.125f);

    // Row softmax in place
    softmax_k<<<BATCH*HEADS*SEQ, 256>>>(probs);

    // Context: per (b,h): probs @ v -> ctx scratch ([B,S,D] layout)
    gemm_k<2048,64,2048,128,64,16,8,4,2><<<dim3(1,16,32), t>>>(probs, gv, nullptr, gctx, 1.f);

    // Output projection: ctx @ Wo^T + bo -> out region
    gemm_k<4096,1024,1024,128,128,16,8,8,0><<<dim3(8,32,1), t>>>(gctx, Wo, bo, out, 1.f);
}

// round 2
// speedup vs baseline: 1.8753x; 1.8753x over previous
#include <cuda_runtime.h>
#include <math.h>
#include <stdint.h>

#define BATCH 2
#define SEQ 2048
#define DMODEL 1024
#define HEADS 16
#define DK 64

// Scratch: q,k,v,ctx in [B,S,D] layout (head h occupies columns h*64..h*64+63)
static __device__ float g_q[BATCH*SEQ*DMODEL];
static __device__ float g_k[BATCH*SEQ*DMODEL];
static __device__ float g_v[BATCH*SEQ*DMODEL];
static __device__ float g_ctx[BATCH*SEQ*DMODEL];

__device__ __forceinline__ float to_tf32(float x) {
    float y;
    asm("cvt.rna.tf32.f32 %0, %1;" : "=f"(y) : "f"(x));
    return y;
}

__device__ __forceinline__ void mma8(float* d, const uint32_t* a, const uint32_t* b) {
    asm volatile(
        "mma.sync.aligned.m16n8k8.row.col.f32.tf32.tf32.f32 "
        "{%0,%1,%2,%3}, {%4,%5,%6,%7}, {%8,%9}, {%0,%1,%2,%3};\n"
        : "+f"(d[0]), "+f"(d[1]), "+f"(d[2]), "+f"(d[3])
        : "r"(a[0]), "r"(a[1]), "r"(a[2]), "r"(a[3]),
          "r"(b[0]), "r"(b[1]));
}

// Tensor-core TF32 GEMM, C = A @ op(B) * scale (+ bias).
// MODE 0: C[M,N] = A[M,K] @ B[N,K]^T + bias               (projections)
// MODE 1: per-(b,h) scores = q @ k^T * scale -> probs     (z = b*H+h)
// MODE 2: per-(b,h) ctx = probs @ v (B is [K,N])          (z = b*H+h)
template<int M,int N,int K,int BM,int BN,int BK,int WM,int WN,int MODE>
__global__ void __launch_bounds__((BM/WM)*(BN/WN)*32)
mma_gemm(const float* __restrict__ A0, const float* __restrict__ B0,
         const float* __restrict__ bias, float* __restrict__ C0, float scale)
{
    constexpr int THREADS = (BM/WM)*(BN/WN)*32;
    constexpr int MI = WM/16, NI = WN/8;
    constexpr bool TRANSB = (MODE != 2);

    const int tid   = threadIdx.x;
    const int tileN = blockIdx.x * BN;
    const int tileM = blockIdx.y * BM;
    const int z     = blockIdx.z;

    const float* A  = A0;
    const float* Bp = B0;
    float*       C  = C0;
    int lda, ldb, ldc;
    if (MODE == 0) {
        lda = K; ldb = K; ldc = N;
    } else if (MODE == 1) {
        const int b = z / HEADS, h = z % HEADS;
        const size_t off = (size_t)b*SEQ*DMODEL + (size_t)h*DK;
        A = A0 + off; Bp = B0 + off;
        lda = DMODEL; ldb = DMODEL;
        C = C0 + (size_t)z*SEQ*SEQ; ldc = SEQ;
    } else {
        const int b = z / HEADS, h = z % HEADS;
        A = A0 + (size_t)z*SEQ*SEQ; lda = SEQ;
        Bp = B0 + (size_t)b*SEQ*DMODEL + (size_t)h*DK; ldb = DMODEL;
        C  = C0 + (size_t)b*SEQ*DMODEL + (size_t)h*DK; ldc = DMODEL;
    }

    // +8 word pad: fragment LDS bank = (8*tig + gid) % 32 -> conflict-free
    __shared__ __align__(16) float As[BK][BM+8];
    __shared__ __align__(16) float Bs[BK][BN+8];

    const int warp = tid >> 5, lane = tid & 31;
    const int gid  = lane >> 2, tig = lane & 3;
    const int wM   = (warp % (BM/WM)) * WM;
    const int wN   = (warp / (BM/WM)) * WN;

    float acc[MI][NI][4];
    #pragma unroll
    for (int i = 0; i < MI; ++i)
        #pragma unroll
        for (int j = 0; j < NI; ++j)
            #pragma unroll
            for (int r = 0; r < 4; ++r)
                acc[i][j][r] = 0.f;

    for (int k0 = 0; k0 < K; k0 += BK) {
        // A tile: rows m, cols k0..k0+BK -> As[k][m] (transposed), tf32-converted
        #pragma unroll 2
        for (int i = tid; i < (BM*BK)/4; i += THREADS) {
            const int m  = i / (BK/4);
            const int k4 = (i % (BK/4)) * 4;
            float4 va = *(const float4*)(A + (size_t)(tileM+m)*lda + k0 + k4);
            As[k4+0][m] = to_tf32(va.x); As[k4+1][m] = to_tf32(va.y);
            As[k4+2][m] = to_tf32(va.z); As[k4+3][m] = to_tf32(va.w);
        }
        if (TRANSB) {
            // B[N,K]: (n,k) at Bp[n*ldb+k] -> Bs[k][n]
            #pragma unroll 2
            for (int i = tid; i < (BN*BK)/4; i += THREADS) {
                const int n  = i / (BK/4);
                const int k4 = (i % (BK/4)) * 4;
                float4 vb = *(const float4*)(Bp + (size_t)(tileN+n)*ldb + k0 + k4);
                Bs[k4+0][n] = to_tf32(vb.x); Bs[k4+1][n] = to_tf32(vb.y);
                Bs[k4+2][n] = to_tf32(vb.z); Bs[k4+3][n] = to_tf32(vb.w);
            }
        } else {
            // B[K,N]: (k,n) at Bp[k*ldb+n] -> Bs[k][n]
            #pragma unroll 2
            for (int i = tid; i < (BK*BN)/4; i += THREADS) {
                const int kk = i / (BN/4);
                const int n4 = (i % (BN/4)) * 4;
                float4 vb = *(const float4*)(Bp + (size_t)(k0+kk)*ldb + tileN + n4);
                Bs[kk][n4+0] = to_tf32(vb.x); Bs[kk][n4+1] = to_tf32(vb.y);
                Bs[kk][n4+2] = to_tf32(vb.z); Bs[kk][n4+3] = to_tf32(vb.w);
            }
        }
        __syncthreads();

        #pragma unroll
        for (int ks = 0; ks < BK; ks += 8) {
            uint32_t af[MI][4], bf[NI][2];
            #pragma unroll
            for (int mi = 0; mi < MI; ++mi) {
                const int m0 = wM + mi*16;
                af[mi][0] = __float_as_uint(As[ks+tig  ][m0+gid  ]);
                af[mi][1] = __float_as_uint(As[ks+tig  ][m0+gid+8]);
                af[mi][2] = __float_as_uint(As[ks+tig+4][m0+gid  ]);
                af[mi][3] = __float_as_uint(As[ks+tig+4][m0+gid+8]);
            }
            #pragma unroll
            for (int ni = 0; ni < NI; ++ni) {
                const int n0 = wN + ni*8;
                bf[ni][0] = __float_as_uint(Bs[ks+tig  ][n0+gid]);
                bf[ni][1] = __float_as_uint(Bs[ks+tig+4][n0+gid]);
            }
            #pragma unroll
            for (int mi = 0; mi < MI; ++mi)
                #pragma unroll
                for (int ni = 0; ni < NI; ++ni)
                    mma8(acc[mi][ni], af[mi], bf[ni]);
        }
        __syncthreads();
    }

    // Epilogue: c0/c1 adjacent columns -> float2 stores
    #pragma unroll
    for (int mi = 0; mi < MI; ++mi) {
        const int r0 = tileM + wM + mi*16 + gid;
        #pragma unroll
        for (int ni = 0; ni < NI; ++ni) {
            const int c0 = tileN + wN + ni*8 + tig*2;
            float v0 = acc[mi][ni][0] * scale;
            float v1 = acc[mi][ni][1] * scale;
            float v2 = acc[mi][ni][2] * scale;
            float v3 = acc[mi][ni][3] * scale;
            if (MODE == 0) {
                const float b0 = bias[c0], b1 = bias[c0+1];
                v0 += b0; v1 += b1; v2 += b0; v3 += b1;
            }
            *(float2*)(C + (size_t)r0*ldc + c0)     = make_float2(v0, v1);
            *(float2*)(C + (size_t)(r0+8)*ldc + c0) = make_float2(v2, v3);
        }
    }
}

// In-place row softmax over rows of length SEQ=2048. One block (256 thr) per row.
__global__ void __launch_bounds__(256) softmax_k(float* __restrict__ p)
{
    const int row = blockIdx.x;
    float* r = p + (size_t)row * SEQ;
    const int tid = threadIdx.x;

    float x[8];
    float mx = -1e30f;
    #pragma unroll
    for (int i = 0; i < 8; ++i) {
        x[i] = r[tid + i*256];
        mx = fmaxf(mx, x[i]);
    }
    #pragma unroll
    for (int o = 16; o; o >>= 1) mx = fmaxf(mx, __shfl_xor_sync(0xffffffffu, mx, o));

    __shared__ float red[8];
    if ((tid & 31) == 0) red[tid >> 5] = mx;
    __syncthreads();
    float m = red[0];
    #pragma unroll
    for (int j = 1; j < 8; ++j) m = fmaxf(m, red[j]);
    __syncthreads();

    float s = 0.f;
    #pragma unroll
    for (int i = 0; i < 8; ++i) { x[i] = expf(x[i] - m); s += x[i]; }
    #pragma unroll
    for (int o = 16; o; o >>= 1) s += __shfl_xor_sync(0xffffffffu, s, o);
    if ((tid & 31) == 0) red[tid >> 5] = s;
    __syncthreads();
    float tot = 0.f;
    #pragma unroll
    for (int j = 0; j < 8; ++j) tot += red[j];
    const float inv = 1.0f / tot;

    #pragma unroll
    for (int i = 0; i < 8; ++i) r[tid + i*256] = x[i] * inv;
}

extern "C" void kernel_launch(void* const* d_in, const int* in_sizes, int n_in,
                              void* d_out, int out_size)
{
    const float* Q  = (const float*)d_in[0];
    const float* K_ = (const float*)d_in[1];
    const float* V  = (const float*)d_in[2];
    const float* Wq = (const float*)d_in[3];
    const float* bq = (const float*)d_in[4];
    const float* Wk = (const float*)d_in[5];
    const float* bk = (const float*)d_in[6];
    const float* Wv = (const float*)d_in[7];
    const float* bv = (const float*)d_in[8];
    const float* Wo = (const float*)d_in[9];
    const float* bo = (const float*)d_in[10];

    float* probs = (float*)d_out;                                  // [B,H,S,S]
    float* out   = probs + (size_t)BATCH*HEADS*SEQ*SEQ;            // [B,S,D]

    float *gq, *gk, *gv, *gctx;
    cudaGetSymbolAddress((void**)&gq,  g_q);
    cudaGetSymbolAddress((void**)&gk,  g_k);
    cudaGetSymbolAddress((void**)&gv,  g_v);
    cudaGetSymbolAddress((void**)&gctx, g_ctx);

    // Projections: [4096,1024] @ W^T + b -> scratch
    mma_gemm<4096,1024,1024,128,128,32,64,32,0><<<dim3(8,32,1), 256>>>(Q,  Wq, bq, gq,  1.f);
    mma_gemm<4096,1024,1024,128,128,32,64,32,0><<<dim3(8,32,1), 256>>>(K_, Wk, bk, gk,  1.f);
    mma_gemm<4096,1024,1024,128,128,32,64,32,0><<<dim3(8,32,1), 256>>>(V,  Wv, bv, gv,  1.f);

    // Scores: per (b,h): q @ k^T * (1/8) -> probs region (raw scores)
    mma_gemm<2048,2048,64,128,128,32,64,32,1><<<dim3(16,16,32), 256>>>(gq, gk, nullptr, probs, 0.125f);

    // Row softmax in place
    softmax_k<<<BATCH*HEADS*SEQ, 256>>>(probs);

    // Context: per (b,h): probs @ v -> ctx scratch
    mma_gemm<2048,64,2048,128,64,32,32,32,2><<<dim3(1,16,32), 256>>>(probs, gv, nullptr, gctx, 1.f);

    // Output projection: ctx @ Wo^T + bo -> out region
    mma_gemm<4096,1024,1024,128,128,32,64,32,0><<<dim3(8,32,1), 256>>>(gctx, Wo, bo, out, 1.f);
}

// round 3
// speedup vs baseline: 2.6142x; 1.3940x over previous
#include <cuda_runtime.h>
#include <math.h>
#include <stdint.h>

#define BATCH 2
#define SEQ 2048
#define DMODEL 1024
#define HEADS 16
#define DK 64
#define NROWS (BATCH*HEADS*SEQ)   // 65536 softmax rows
#define NTILES 16                 // 2048/128 col tiles

// Scratch ([B,S,D] layout; head h = columns h*64..h*64+63)
static __device__ float g_q[BATCH*SEQ*DMODEL];
static __device__ float g_k[BATCH*SEQ*DMODEL];
static __device__ float g_v[BATCH*SEQ*DMODEL];
static __device__ float g_ctx[BATCH*SEQ*DMODEL];
// softmax stats
static __device__ float g_pmax[NROWS*NTILES];
static __device__ float g_psum[NROWS*NTILES];
static __device__ float g_m[NROWS];
static __device__ float g_inv[NROWS];

__device__ __forceinline__ float to_tf32(float x) {
    float y;
    asm("cvt.rna.tf32.f32 %0, %1;" : "=f"(y) : "f"(x));
    return y;
}
__device__ __forceinline__ uint32_t tf32u(float x) {
    return __float_as_uint(to_tf32(x));
}
__device__ __forceinline__ void mma8(float* d, const uint32_t* a, const uint32_t* b) {
    asm volatile(
        "mma.sync.aligned.m16n8k8.row.col.f32.tf32.tf32.f32 "
        "{%0,%1,%2,%3}, {%4,%5,%6,%7}, {%8,%9}, {%0,%1,%2,%3};\n"
        : "+f"(d[0]), "+f"(d[1]), "+f"(d[2]), "+f"(d[3])
        : "r"(a[0]), "r"(a[1]), "r"(a[2]), "r"(a[3]),
          "r"(b[0]), "r"(b[1]));
}
__device__ __forceinline__ void cp16(uint32_t dst_smem, const void* src) {
    asm volatile("cp.async.cg.shared.global [%0], [%1], 16;\n" :: "r"(dst_smem), "l"(src));
}
__device__ __forceinline__ void cp_commit() { asm volatile("cp.async.commit_group;\n"); }
template<int N> __device__ __forceinline__ void cp_wait() {
    asm volatile("cp.async.wait_group %0;\n" :: "n"(N));
}

// ---------------------------------------------------------------------------
// Projection GEMM: C[4096,1024] = A @ W^T + bias, z selects (A,W,b,C) triple.
// CTA 128x128, BK=32, 8 warps (64x32), cp.async 2-stage pipeline.
// smem layout (words): As[2][128][36] at 0/4608, Ws[2][128][36] at 9216/13824.
// ---------------------------------------------------------------------------
__global__ void __launch_bounds__(256, 2)
proj_gemm(const float* __restrict__ A0, const float* __restrict__ A1, const float* __restrict__ A2,
          const float* __restrict__ W0, const float* __restrict__ W1, const float* __restrict__ W2,
          const float* __restrict__ B0, const float* __restrict__ B1, const float* __restrict__ B2,
          float* __restrict__ C0, float* __restrict__ C1, float* __restrict__ C2)
{
    extern __shared__ __align__(16) float sm[];
    const int tid = threadIdx.x;
    const int z = blockIdx.z;
    const float* A    = (z==0) ? A0 : ((z==1) ? A1 : A2);
    const float* W    = (z==0) ? W0 : ((z==1) ? W1 : W2);
    const float* bias = (z==0) ? B0 : ((z==1) ? B1 : B2);
    float*       C    = (z==0) ? C0 : ((z==1) ? C1 : C2);
    const int tileN = blockIdx.x * 128;
    const int tileM = blockIdx.y * 128;

    const int warp = tid >> 5, lane = tid & 31, gid = lane >> 2, tig = lane & 3;
    const int wM = (warp & 1) * 64, wN = (warp >> 1) * 32;

    const uint32_t smb = (uint32_t)__cvta_generic_to_shared(sm);

    float acc[4][4][4];
    #pragma unroll
    for (int i=0;i<4;++i)ch:
    ;
    #pragma unroll
    for (int i=0;i<4;++i)
        #pragma unroll
        for (int j=0;j<4;++j)
            #pragma unroll
            for (int r=0;r<4;++r) acc[i][j][r]=0.f;

    // prologue: stage 0
    #pragma unroll
    for (int i=0;i<4;++i) {
        int e = tid + i*256, m = e>>3, kq = e&7;
        cp16(smb + (uint32_t)((m*36 + kq*4)*4),          A + (size_t)(tileM+m)*1024 + kq*4);
        cp16(smb + (uint32_t)((9216 + m*36 + kq*4)*4),   W + (size_t)(tileN+m)*1024 + kq*4);
    }
    cp_commit();

    for (int it = 0; it < 32; ++it) {
        const int cur = it & 1;
        if (it < 31) {
            const int nb = cur ^ 1;
            const int k0 = (it+1)*32;
            #pragma unroll
            for (int i=0;i<4;++i) {
                int e = tid + i*256, m = e>>3, kq = e&7;
                cp16(smb + (uint32_t)((nb*4608 + m*36 + kq*4)*4),        A + (size_t)(tileM+m)*1024 + k0 + kq*4);
                cp16(smb + (uint32_t)((9216 + nb*4608 + m*36 + kq*4)*4), W + (size_t)(tileN+m)*1024 + k0 + kq*4);
            }
            cp_commit();
            cp_wait<1>();
        } else {
            cp_wait<0>();
        }
        __syncthreads();

        const float* As = sm + cur*4608;
        const float* Ws = sm + 9216 + cur*4608;
        #pragma unroll
        for (int ks = 0; ks < 32; ks += 8) {
            uint32_t af[4][4], bf[4][2];
            #pragma unroll
            for (int mi=0;mi<4;++mi) {
                const int m0 = wM + mi*16;
                af[mi][0] = tf32u(As[(m0+gid  )*36 + ks+tig  ]);
                af[mi][1] = tf32u(As[(m0+gid+8)*36 + ks+tig  ]);
                af[mi][2] = tf32u(As[(m0+gid  )*36 + ks+tig+4]);
                af[mi][3] = tf32u(As[(m0+gid+8)*36 + ks+tig+4]);
            }
            #pragma unroll
            for (int ni=0;ni<4;++ni) {
                const int n0 = wN + ni*8;
                bf[ni][0] = tf32u(Ws[(n0+gid)*36 + ks+tig  ]);
                bf[ni][1] = tf32u(Ws[(n0+gid)*36 + ks+tig+4]);
            }
            #pragma unroll
            for (int mi=0;mi<4;++mi)
                #pragma unroll
                for (int ni=0;ni<4;++ni)
                    mma8(acc[mi][ni], af[mi], bf[ni]);
        }
        __syncthreads();
    }

    #pragma unroll
    for (int mi=0;mi<4;++mi) {
        const int r0 = tileM + wM + mi*16 + gid;
        #pragma unroll
        for (int ni=0;ni<4;++ni) {
            const int c0 = tileN + wN + ni*8 + tig*2;
            const float b0 = bias[c0], b1 = bias[c0+1];
            *(float2*)(C + (size_t)r0*1024 + c0)     = make_float2(acc[mi][ni][0]+b0, acc[mi][ni][1]+b1);
            *(float2*)(C + (size_t)(r0+8)*1024 + c0) = make_float2(acc[mi][ni][2]+b0, acc[mi][ni][3]+b1);
        }
    }
}

// ---------------------------------------------------------------------------
// Scores + per-tile row stats. Per (z, rowtile, ntile): 128x128 tile of
// scaled scores written raw to probs; per-row tile-max and tile-sumexp
// partials written to g_pmax/g_psum.
// smem: Qs[128][68] at 0, Ks[128][68] at 8704 (words). Stats reuse sm base.
// ---------------------------------------------------------------------------
__global__ void __launch_bounds__(256, 2)
scores_stats(const float* __restrict__ q, const float* __restrict__ kmat,
             float* __restrict__ probs, float* __restrict__ pmax, float* __restrict__ psum)
{
    extern __shared__ __align__(16) float sm[];
    const int tid = threadIdx.x;
    const int ntile = blockIdx.x, rowtile = blockIdx.y, z = blockIdx.z;
    const int b = z >> 4, h = z & 15;

    const float* Qp = q    + ((size_t)b*SEQ + rowtile*128)*DMODEL + h*DK;
    const float* Kp = kmat + ((size_t)b*SEQ + ntile*128)*DMODEL + h*DK;
    const uint32_t smb = (uint32_t)__cvta_generic_to_shared(sm);

    #pragma unroll
    for (int i=0;i<8;++i) {
        int e = tid + i*256, m = e>>4, kq = e&15;
        cp16(smb + (uint32_t)((m*68 + kq*4)*4),          Qp + (size_t)m*1024 + kq*4);
        cp16(smb + (uint32_t)((8704 + m*68 + kq*4)*4),   Kp + (size_t)m*1024 + kq*4);
    }
    cp_commit(); cp_wait<0>();
    __syncthreads();

    const int warp = tid >> 5, lane = tid & 31, gid = lane >> 2, tig = lane & 3;
    const int wM = (warp & 1) * 64, wN = (warp >> 1) * 32, warp_n = warp >> 1;

    float acc[4][4][4];
    #pragma unroll
    for (int i=0;i<4;++i)
        #pragma unroll
        for (int j=0;j<4;++j)
            #pragma unroll
            for (int r=0;r<4;++r) acc[i][j][r]=0.f;

    const float* Qs = sm;
    const float* Ks = sm + 8704;
    #pragma unroll
    for (int ks = 0; ks < 64; ks += 8) {
        uint32_t af[4][4], bf[4][2];
        #pragma unroll
        for (int mi=0;mi<4;++mi) {
            const int m0 = wM + mi*16;
            af[mi][0] = tf32u(Qs[(m0+gid  )*68 + ks+tig  ]);
            af[mi][1] = tf32u(Qs[(m0+gid+8)*68 + ks+tig  ]);
            af[mi][2] = tf32u(Qs[(m0+gid  )*68 + ks+tig+4]);
            af[mi][3] = tf32u(Qs[(m0+gid+8)*68 + ks+tig+4]);
        }
        #pragma unroll
        for (int ni=0;ni<4;++ni) {
            const int n0 = wN + ni*8;
            bf[ni][0] = tf32u(Ks[(n0+gid)*68 + ks+tig  ]);
            bf[ni][1] = tf32u(Ks[(n0+gid)*68 + ks+tig+4]);
        }
        #pragma unroll
        for (int mi=0;mi<4;++mi)
            #pragma unroll
            for (int ni=0;ni<4;++ni)
                mma8(acc[mi][ni], af[mi], bf[ni]);
    }

    // scale
    #pragma unroll
    for (int mi=0;mi<4;++mi)
        #pragma unroll
        for (int ni=0;ni<4;++ni)
            #pragma unroll
            for (int r=0;r<4;++r) acc[mi][ni][r] *= 0.125f;

    // per-thread row stats: rows (mi, half): wM+mi*16+gid (+8 for half=1)
    float rm[4][2], rs[4][2];
    #pragma unroll
    for (int mi=0;mi<4;++mi) {
        #pragma unroll
        for (int hf=0;hf<2;++hf) {
            float mx = -1e30f;
            #pragma unroll
            for (int ni=0;ni<4;++ni)
                mx = fmaxf(mx, fmaxf(acc[mi][ni][hf*2], acc[mi][ni][hf*2+1]));
            mx = fmaxf(mx, __shfl_xor_sync(0xffffffffu, mx, 1));
            mx = fmaxf(mx, __shfl_xor_sync(0xffffffffu, mx, 2));
            float s = 0.f;
            #pragma unroll
            for (int ni=0;ni<4;++ni) {
                s += __expf(acc[mi][ni][hf*2]   - mx);
                s += __expf(acc[mi][ni][hf*2+1] - mx);
            }
            s += __shfl_xor_sync(0xffffffffu, s, 1);
            s += __shfl_xor_sync(0xffffffffu, s, 2);
            rm[mi][hf] = mx; rs[mi][hf] = s;
        }
    }
    __syncthreads();                  // mainloop smem no longer needed
    float2* red = (float2*)sm;        // [4 warp_n][128 rows]
    if (tig == 0) {
        #pragma unroll
        for (int mi=0;mi<4;++mi)
            #pragma unroll
            for (int hf=0;hf<2;++hf) {
                const int row = wM + mi*16 + gid + hf*8;
                red[warp_n*128 + row] = make_float2(rm[mi][hf], rs[mi][hf]);
            }
    }
    __syncthreads();
    if (tid < 128) {
        float2 p0 = red[tid], p1 = red[128+tid], p2 = red[256+tid], p3 = red[384+tid];
        float M = fmaxf(fmaxf(p0.x, p1.x), fmaxf(p2.x, p3.x));
        float S = p0.y*__expf(p0.x-M) + p1.y*__expf(p1.x-M)
                + p2.y*__expf(p2.x-M) + p3.y*__expf(p3.x-M);
        const size_t grow = (size_t)z*SEQ + rowtile*128 + tid;
        pmax[grow*NTILES + ntile] = M;
        psum[grow*NTILES + ntile] = S;
    }

    // write raw scaled scores
    float* Cp = probs + (size_t)z*SEQ*SEQ;
    #pragma unroll
    for (int mi=0;mi<4;++mi) {
        const int r0 = rowtile*128 + wM + mi*16 + gid;
        #pragma unroll
        for (int ni=0;ni<4;++ni) {
            const int c0 = ntile*128 + wN + ni*8 + tig*2;
            *(float2*)(Cp + (size_t)r0*SEQ + c0)     = make_float2(acc[mi][ni][0], acc[mi][ni][1]);
            *(float2*)(Cp + (size_t)(r0+8)*SEQ + c0) = make_float2(acc[mi][ni][2], acc[mi][ni][3]);
        }
    }
}

// ---------------------------------------------------------------------------
// Reduce per-tile stats -> per-row (max, 1/sum)
// ---------------------------------------------------------------------------
__global__ void __launch_bounds__(256)
reduce_stats(const float* __restrict__ pmax, const float* __restrict__ psum,
             float* __restrict__ gm, float* __restrict__ ginv)
{
    const int r = blockIdx.x * 256 + threadIdx.x;
    float mx[NTILES], sx[NTILES];
    #pragma unroll
    for (int t=0;t<NTILES;++t) { mx[t]=pmax[(size_t)r*NTILES+t]; sx[t]=psum[(size_t)r*NTILES+t]; }
    float M = -1e30f;
    #pragma unroll
    for (int t=0;t<NTILES;++t) M = fmaxf(M, mx[t]);
    float S = 0.f;
    #pragma unroll
    for (int t=0;t<NTILES;++t) S += sx[t]*__expf(mx[t]-M);
    gm[r] = M; ginv[r] = 1.f/S;
}

// ---------------------------------------------------------------------------
// Fused normalize + ctx. Per (rowtile, z): loop over 16 col tiles:
// read raw scores, p = __expf(s-m)*inv, write probs in place, STS tf32(p),
// mma accumulate ctx(128x64) with V tile (cp.async).
// smem (words): Ps[128][132] at 0, Vs[128][72] at 16896, m[128] at 26112,
// inv[128] at 26240. 8 warps, warp tile 16x64 (MI=1, NI=8).
// ---------------------------------------------------------------------------
__global__ void __launch_bounds__(256, 2)
norm_ctx(float* __restrict__ probs, const float* __restrict__ v,
         const float* __restrict__ gm, const float* __restrict__ ginv,
         float* __restrict__ ctx)
{
    extern __shared__ __align__(16) float sm[];
    float* Ps  = sm;
    float* Vs  = sm + 16896;
    float* smm = sm + 26112;
    float* smi = sm + 26240;

    const int tid = threadIdx.x, rowtile = blockIdx.x, z = blockIdx.y;
    const int b = z >> 4, h = z & 15;
    const size_t grow0 = (size_t)z*SEQ + rowtile*128;
    if (tid < 128) { smm[tid] = gm[grow0+tid]; smi[tid] = ginv[grow0+tid]; }

    const int warp = tid >> 5, lane = tid & 31, gid = lane >> 2, tig = lane & 3;
    const int m0 = warp * 16;
    const uint32_t smb = (uint32_t)__cvta_generic_to_shared(sm);

    const float* Vp0 = v + (size_t)b*SEQ*DMODEL + h*DK;
    float* P0 = probs + (size_t)z*SEQ*SEQ + (size_t)(rowtile*128)*SEQ;

    float acc[8][4];
    #pragma unroll
    for (int i=0;i<8;++i)
        #pragma unroll
        for (int r=0;r<4;++r) acc[i][r]=0.f;

    __syncthreads();

    for (int nt = 0; nt < 16; ++nt) {
        // V tile (128 rows x 64 cols) via cp.async
        #pragma unroll
        for (int i=0;i<8;++i) {
            int e = tid + i*256, r = e>>4, kq = e&15;
            cp16(smb + (uint32_t)((16896 + r*72 + kq*4)*4),
                 Vp0 + (size_t)(nt*128+r)*1024 + kq*4);
        }
        cp_commit();

        // normalize probs tile, stash tf32 into Ps
        #pragma unroll 4
        for (int j=0;j<16;++j) {
            const int e = tid + j*256, row = e>>5, c4 = e&31;
            float4* gp = (float4*)(P0 + (size_t)row*SEQ + nt*128 + c4*4);
            float4 x = *gp;
            const float M = smm[row], IV = smi[row];
            x.x = __expf(x.x - M)*IV;
            x.y = __expf(x.y - M)*IV;
            x.z = __expf(x.z - M)*IV;
            x.w = __expf(x.w - M)*IV;
            *gp = x;
            float4 t;
            t.x = to_tf32(x.x); t.y = to_tf32(x.y);
            t.z = to_tf32(x.z); t.w = to_tf32(x.w);
            *(float4*)(Ps + row*132 + c4*4) = t;
        }
        cp_wait<0>();
        __syncthreads();

        #pragma unroll 4
        for (int ks = 0; ks < 128; ks += 8) {
            uint32_t af[4], bf[8][2];
            af[0] = __float_as_uint(Ps[(m0+gid  )*132 + ks+tig  ]);
            af[1] = __float_as_uint(Ps[(m0+gid+8)*132 + ks+tig  ]);
            af[2] = __float_as_uint(Ps[(m0+gid  )*132 + ks+tig+4]);
            af[3] = __float_as_uint(Ps[(m0+gid+8)*132 + ks+tig+4]);
            #pragma unroll
            for (int ni=0;ni<8;++ni) {
                const int n0 = ni*8;
                bf[ni][0] = tf32u(Vs[(ks+tig  )*72 + n0+gid]);
                bf[ni][1] = tf32u(Vs[(ks+tig+4)*72 + n0+gid]);
            }
            #pragma unroll
            for (int ni=0;ni<8;++ni)
                mma8(acc[ni], af, bf[ni]);
        }
        __syncthreads();
    }

    float* Cp = ctx + ((size_t)b*SEQ + rowtile*128)*DMODEL + h*DK;
    #pragma unroll
    for (int ni=0;ni<8;++ni) {
        const int c0 = ni*8 + tig*2;
        *(float2*)(Cp + (size_t)(m0+gid)*1024 + c0)   = make_float2(acc[ni][0], acc[ni][1]);
        *(float2*)(Cp + (size_t)(m0+gid+8)*1024 + c0) = make_float2(acc[ni][2], acc[ni][3]);
    }
}

// ---------------------------------------------------------------------------
extern "C" void kernel_launch(void* const* d_in, const int* in_sizes, int n_in,
                              void* d_out, int out_size)
{
    const float* Q  = (const float*)d_in[0];
    const float* K_ = (const float*)d_in[1];
    const float* V  = (const float*)d_in[2];
    const float* Wq = (const float*)d_in[3];
    const float* bq = (const float*)d_in[4];
    const float* Wk = (const float*)d_in[5];
    const float* bk = (const float*)d_in[6];
    const float* Wv = (const float*)d_in[7];
    const float* bv = (const float*)d_in[8];
    const float* Wo = (const float*)d_in[9];
    const float* bo = (const float*)d_in[10];

    float* probs = (float*)d_out;                         // [B,H,S,S]
    float* out   = probs + (size_t)BATCH*HEADS*SEQ*SEQ;   // [B,S,D]

    float *gq, *gk, *gv, *gctx, *gpm, *gps, *gm, *gi;
    cudaGetSymbolAddress((void**)&gq,  g_q);
    cudaGetSymbolAddress((void**)&gk,  g_k);
    cudaGetSymbolAddress((void**)&gv,  g_v);
    cudaGetSymbolAddress((void**)&gctx, g_ctx);
    cudaGetSymbolAddress((void**)&gpm, g_pmax);
    cudaGetSymbolAddress((void**)&gps, g_psum);
    cudaGetSymbolAddress((void**)&gm,  g_m);
    cudaGetSymbolAddress((void**)&gi,  g_inv);

    const int SM_PROJ  = 18432 * 4;   // 73728 B
    const int SM_SCORE = 17408 * 4;   // 69632 B
    const int SM_NCTX  = 26368 * 4;   // 105472 B
    cudaFuncSetAttribute(proj_gemm,    cudaFuncAttributeMaxDynamicSharedMemorySize, SM_PROJ);
    cudaFuncSetAttribute(scores_stats, cudaFuncAttributeMaxDynamicSharedMemorySize, SM_SCORE);
    cudaFuncSetAttribute(norm_ctx,     cudaFuncAttributeMaxDynamicSharedMemorySize, SM_NCTX);

    // 1) Q,K,V projections in one launch (z selects)
    proj_gemm<<<dim3(8,32,3), 256, SM_PROJ>>>(Q, K_, V, Wq, Wk, Wv, bq, bk, bv, gq, gk, gv);

    // 2) scores (raw, scaled) + per-tile row stats
    scores_stats<<<dim3(16,16,32), 256, SM_SCORE>>>(gq, gk, probs, gpm, gps);

    // 3) per-row (max, 1/sum)
    reduce_stats<<<dim3(NROWS/256), 256>>>(gpm, gps, gm, gi);

    // 4) normalize probs in place + ctx = probs @ v
    norm_ctx<<<dim3(16,32), 256, SM_NCTX>>>(probs, gv, gm, gi, gctx);

    // 5) output projection
    proj_gemm<<<dim3(8,32,1), 256, SM_PROJ>>>(gctx, gctx, gctx, Wo, Wo, Wo, bo, bo, bo, out, out, out);
}